// round 13
// baseline (speedup 1.0000x reference)
#include <cuda_runtime.h>
#include <cuda_bf16.h>
#include <math.h>
#include <stdint.h>

#define NMAX 100000
#define EMAX 1600000

// ---------------- scratch (static __device__, per harness rules) -------------
__device__ float g_h1[NMAX * 64];
__device__ float g_asrc1[NMAX * 8];
__device__ float g_adst1[NMAX * 8];
__device__ float g_hf1[NMAX * 64];
__device__ float g_asrc2[NMAX];
__device__ float g_adst2[NMAX];

__device__ __nv_bfloat16 g_w1h[64 * 512];   // W1 transposed [n][k], bf16 hi
__device__ __nv_bfloat16 g_w1l[64 * 512];   // W1 transposed [n][k], bf16 lo
__device__ float g_vs2[64];                 // W2 @ att_src2
__device__ float g_vd2[64];                 // W2 @ att_dst2

__device__ int g_counts[NMAX];
__device__ int g_cursor[NMAX];
__device__ int g_bsum[256];
__device__ int g_rowstart[NMAX + 1];
__device__ int g_srcs[EMAX];

// =======================  helpers  ==========================================

__device__ __forceinline__ uint32_t smem_u32(const void* p) {
    uint32_t a;
    asm("{ .reg .u64 t; cvta.to.shared.u64 t, %1; cvt.u32.u64 %0, t; }" : "=r"(a) : "l"(p));
    return a;
}

#define CP_ASYNC16(dst, src) \
    asm volatile("cp.async.cg.shared.global [%0], [%1], 16;" :: "r"(dst), "l"(src) : "memory")
#define CP_COMMIT() asm volatile("cp.async.commit_group;" ::: "memory")
#define CP_WAIT0()  asm volatile("cp.async.wait_group 0;" ::: "memory")

#define LDSM4(r, a) \
    asm volatile("ldmatrix.sync.aligned.m8n8.x4.shared.b16 {%0,%1,%2,%3}, [%4];" \
                 : "=r"((r)[0]), "=r"((r)[1]), "=r"((r)[2]), "=r"((r)[3]) : "r"(a))

__device__ __forceinline__ void mma_bf16(float& c0, float& c1, float& c2, float& c3,
                                         uint32_t a0, uint32_t a1, uint32_t a2, uint32_t a3,
                                         uint32_t b0, uint32_t b1) {
    asm volatile("mma.sync.aligned.m16n8k16.row.col.f32.bf16.bf16.f32 "
                 "{%0,%1,%2,%3}, {%4,%5,%6,%7}, {%8,%9}, {%0,%1,%2,%3};"
                 : "+f"(c0), "+f"(c1), "+f"(c2), "+f"(c3)
                 : "r"(a0), "r"(a1), "r"(a2), "r"(a3), "r"(b0), "r"(b1));
}

__device__ __forceinline__ void split_bf16(float v, __nv_bfloat16& hi, __nv_bfloat16& lo) {
    hi = __float2bfloat16(v);
    lo = __float2bfloat16(v - __bfloat162float(hi));
}
__device__ __forceinline__ uint32_t pack2(__nv_bfloat16 a, __nv_bfloat16 b) {
    return (uint32_t)__bfloat16_as_ushort(a) | ((uint32_t)__bfloat16_as_ushort(b) << 16);
}

// =======================  CSR build  ========================================

__global__ void hist_kernel(const int* __restrict__ ei, int E) {
    int e = blockIdx.x * blockDim.x + threadIdx.x;
    if (e >= E) return;
    atomicAdd(&g_counts[ei[E + e]], 1);
}

__global__ void scan_part1(int n) {
    __shared__ int sh[1024];
    int i = blockIdx.x * 1024 + threadIdx.x;
    sh[threadIdx.x] = (i < n) ? g_counts[i] : 0;
    __syncthreads();
#pragma unroll
    for (int off = 512; off; off >>= 1) {
        if (threadIdx.x < off) sh[threadIdx.x] += sh[threadIdx.x + off];
        __syncthreads();
    }
    if (threadIdx.x == 0) g_bsum[blockIdx.x] = sh[0];
}

__global__ void scan_part23(int nb, int n, int E) {
    __shared__ int sh[1024];
    __shared__ int soff;
    int t = threadIdx.x;
    int b = blockIdx.x;
    if (t < 32) {
        int acc = 0;
        for (int i = t; i < b; i += 32) acc += g_bsum[i];
#pragma unroll
        for (int o = 16; o; o >>= 1) acc += __shfl_xor_sync(0xffffffffu, acc, o);
        if (t == 0) soff = acc;
    }
    int i = b * 1024 + t;
    int v = (i < n) ? g_counts[i] : 0;
    sh[t] = v;
    __syncthreads();
#pragma unroll
    for (int off = 1; off < 1024; off <<= 1) {
        int add = (t >= off) ? sh[t - off] : 0;
        __syncthreads();
        sh[t] += add;
        __syncthreads();
    }
    if (i < n) {
        int ex = sh[t] - v + soff;
        g_rowstart[i] = ex;
        g_cursor[i]   = ex;
    }
    if (b == nb - 1 && t == 0) g_rowstart[n] = E;
}

__global__ void scatter_kernel(const int* __restrict__ ei, int E) {
    int e = blockIdx.x * blockDim.x + threadIdx.x;
    if (e >= E) return;
    int src = ei[e];
    int dst = ei[E + e];
    int pos = atomicAdd(&g_cursor[dst], 1);
    g_srcs[pos] = src;
}

// ===================  W1 prep: transpose + bf16 hi/lo split  =================
__global__ void wprep_kernel(const float* __restrict__ W1) {
    int i = blockIdx.x * 256 + threadIdx.x;   // 32768
    int n = i >> 9, k = i & 511;
    float v = W1[(size_t)k * 64 + n];
    __nv_bfloat16 h, l;
    split_bf16(v, h, l);
    g_w1h[i] = h;
    g_w1l[i] = l;
}

// ===================  W2 prep: v_s = W2 @ att_s2, v_d = W2 @ att_d2 ==========
__global__ void wprep2_kernel(const float* __restrict__ W2,
                              const float* __restrict__ as2,
                              const float* __restrict__ ad2) {
    int k = threadIdx.x;              // 0..63
    if (k >= 64) return;
    float vs = 0.f, vd = 0.f;
    const float* row = W2 + k * 40;
#pragma unroll
    for (int c = 0; c < 40; c++) {
        float w = row[c];
        vs = fmaf(w, as2[c], vs);
        vd = fmaf(w, ad2[c], vd);
    }
    g_vs2[k] = vs;
    g_vd2[k] = vd;
}

// ============  layer-1 GEMM: bf16 3-pass, double-buffered + ldmatrix  ========
__global__ __launch_bounds__(256, 3)
void gemm1_v2(const float* __restrict__ A, int M, float* __restrict__ C,
              const float* __restrict__ att_s, const float* __restrict__ att_d,
              float* __restrict__ asrc, float* __restrict__ adst) {
    extern __shared__ char dsm[];
    constexpr int STR  = 40;
    constexpr int SZ_A = 128 * STR * 2;       // 10240 B
    constexpr int SZ_B = 64 * STR * 2;        // 5120 B
    constexpr int STAGE = 2 * SZ_A + 2 * SZ_B;// 30720 B
    constexpr int OFF  = 1024;

    const int tid  = threadIdx.x;
    const int lane = tid & 31;
    const int warp = tid >> 5;
    const int wrow = warp >> 1;
    const int wcol = warp & 1;
    const int row0 = blockIdx.x * 128;
    const uint32_t smb = smem_u32(dsm);

    const int arow  = tid & 127;
    const int khalf = (tid >> 7) * 16;
    const int grow  = row0 + arow;
    const bool av   = (grow < M);
    const float* ap = A + (size_t)grow * 512 + khalf;

    float acc[2][4][4];
#pragma unroll
    for (int mt = 0; mt < 2; mt++)
#pragma unroll
        for (int nt = 0; nt < 4; nt++)
#pragma unroll
            for (int r = 0; r < 4; r++) acc[mt][nt][r] = 0.f;

    float rA[16];
    auto ldgA = [&](int kt) {
        if (av) {
#pragma unroll
            for (int q = 0; q < 4; q++)
                *reinterpret_cast<float4*>(&rA[q * 4]) =
                    *reinterpret_cast<const float4*>(ap + kt * 32 + q * 4);
        } else {
#pragma unroll
            for (int q = 0; q < 16; q++) rA[q] = 0.f;
        }
    };
    auto stsA = [&](int st) {
        uint32_t h[8], l[8];
#pragma unroll
        for (int p = 0; p < 8; p++) {
            __nv_bfloat16 h0, l0, h1, l1;
            split_bf16(rA[2 * p], h0, l0);
            split_bf16(rA[2 * p + 1], h1, l1);
            h[p] = pack2(h0, h1);
            l[p] = pack2(l0, l1);
        }
        char* base = dsm + OFF + st * STAGE;
        uint32_t off = (uint32_t)(arow * STR + khalf) * 2;
        *reinterpret_cast<uint4*>(base + off)             = make_uint4(h[0], h[1], h[2], h[3]);
        *reinterpret_cast<uint4*>(base + off + 16)        = make_uint4(h[4], h[5], h[6], h[7]);
        *reinterpret_cast<uint4*>(base + SZ_A + off)      = make_uint4(l[0], l[1], l[2], l[3]);
        *reinterpret_cast<uint4*>(base + SZ_A + off + 16) = make_uint4(l[4], l[5], l[6], l[7]);
    };
    auto cpB = [&](int kt, int st) {
        int nn = tid >> 2, kseg = tid & 3;
        uint32_t dst = smb + OFF + st * STAGE + 2 * SZ_A + (uint32_t)(nn * STR + kseg * 8) * 2;
        CP_ASYNC16(dst,        g_w1h + nn * 512 + kt * 32 + kseg * 8);
        CP_ASYNC16(dst + SZ_B, g_w1l + nn * 512 + kt * 32 + kseg * 8);
    };
    auto compute = [&](int st) {
        uint32_t sb = smb + OFF + st * STAGE;
#pragma unroll
        for (int ks = 0; ks < 2; ks++) {
            uint32_t a0addr = sb + (uint32_t)((wrow * 32 + (lane & 15)) * STR +
                                              (lane >> 4) * 8 + ks * 16) * 2;
            uint32_t ah[2][4], al[2][4];
#pragma unroll
            for (int mt = 0; mt < 2; mt++) {
                uint32_t ad = a0addr + mt * 16 * STR * 2;
                LDSM4(ah[mt], ad);
                LDSM4(al[mt], ad + SZ_A);
            }
#pragma unroll
            for (int np = 0; np < 2; np++) {
                uint32_t bd = sb + 2 * SZ_A +
                              (uint32_t)((wcol * 32 + np * 16 + ((lane >> 4) << 3) + (lane & 7)) * STR +
                                         ks * 16 + (((lane >> 3) & 1) << 3)) * 2;
                uint32_t bh4[4], bl4[4];
                LDSM4(bh4, bd);
                LDSM4(bl4, bd + SZ_B);
#pragma unroll
                for (int n2 = 0; n2 < 2; n2++) {
                    int nt = np * 2 + n2;
                    uint32_t b0h = bh4[n2 * 2], b1h = bh4[n2 * 2 + 1];
                    uint32_t b0l = bl4[n2 * 2], b1l = bl4[n2 * 2 + 1];
#pragma unroll
                    for (int mt = 0; mt < 2; mt++) {
                        float* c = acc[mt][nt];
                        mma_bf16(c[0], c[1], c[2], c[3],
                                 al[mt][0], al[mt][1], al[mt][2], al[mt][3], b0h, b1h);
                        mma_bf16(c[0], c[1], c[2], c[3],
                                 ah[mt][0], ah[mt][1], ah[mt][2], ah[mt][3], b0l, b1l);
                        mma_bf16(c[0], c[1], c[2], c[3],
                                 ah[mt][0], ah[mt][1], ah[mt][2], ah[mt][3], b0h, b1h);
                    }
                }
            }
        }
    };

    ldgA(0);
    cpB(0, 0);
    CP_COMMIT();
    stsA(0);
    CP_WAIT0();
    __syncthreads();

    for (int kt = 0; kt < 16; kt++) {
        int cur = kt & 1;
        if (kt < 15) {
            ldgA(kt + 1);
            cpB(kt + 1, cur ^ 1);
            CP_COMMIT();
        }
        compute(cur);
        if (kt < 15) {
            stsA(cur ^ 1);
            CP_WAIT0();
        }
        __syncthreads();
    }

    const int qt = lane & 3;
    const int rg = lane >> 2;
#pragma unroll
    for (int mt = 0; mt < 2; mt++)
#pragma unroll
        for (int nt = 0; nt < 4; nt++) {
            float* c = acc[mt][nt];
            int r0 = row0 + wrow * 32 + mt * 16 + rg;
            int r1 = r0 + 8;
            int col = wcol * 32 + nt * 8 + qt * 2;
            if (r0 < M)
                *reinterpret_cast<float2*>(&C[(size_t)r0 * 64 + col]) = make_float2(c[0], c[1]);
            if (r1 < M)
                *reinterpret_cast<float2*>(&C[(size_t)r1 * 64 + col]) = make_float2(c[2], c[3]);
            float s0 = __ldg(&att_s[col]), s1 = __ldg(&att_s[col + 1]);
            float d0 = __ldg(&att_d[col]), d1 = __ldg(&att_d[col + 1]);
            float as_a = c[0] * s0 + c[1] * s1;
            float ad_a = c[0] * d0 + c[1] * d1;
            float as_b = c[2] * s0 + c[3] * s1;
            float ad_b = c[2] * d0 + c[3] * d1;
            as_a += __shfl_xor_sync(0xffffffffu, as_a, 1);
            as_a += __shfl_xor_sync(0xffffffffu, as_a, 2);
            ad_a += __shfl_xor_sync(0xffffffffu, ad_a, 1);
            ad_a += __shfl_xor_sync(0xffffffffu, ad_a, 2);
            as_b += __shfl_xor_sync(0xffffffffu, as_b, 1);
            as_b += __shfl_xor_sync(0xffffffffu, as_b, 2);
            ad_b += __shfl_xor_sync(0xffffffffu, ad_b, 1);
            ad_b += __shfl_xor_sync(0xffffffffu, ad_b, 2);
            int head = wcol * 4 + nt;
            if (qt == 0) {
                if (r0 < M) { asrc[r0 * 8 + head] = as_a; adst[r0 * 8 + head] = ad_a; }
                if (r1 < M) { asrc[r1 * 8 + head] = as_b; adst[r1 * 8 + head] = ad_b; }
            }
        }
}

// =======================  layer-1 aggregation (warp per dst)  ===============
// Epilogue now also emits layer-2 logits: asrc2 = hfeat . v_s, adst2 = hfeat . v_d
__global__ void agg1_kernel(const float* __restrict__ b1, int node0, int node1) {
    __shared__ float wsm[8][32][8];
    const int wid  = threadIdx.x >> 5;
    const int lane = threadIdx.x & 31;
    int node = node0 + ((blockIdx.x * blockDim.x + threadIdx.x) >> 5);
    if (node >= node1) return;

    const int myh = lane & 7;
    const int grp = lane >> 3;
    const int h0  = lane >> 3;
    const int h1f = 4 + h0;

    float adst_l = g_adst1[node * 8 + myh];
    float acc0 = 0.f, acc1 = 0.f, wsum = 0.f;

    int beg = g_rowstart[node], end = g_rowstart[node + 1];
    for (int base = beg; base < end; base += 32) {
        int cnt = min(32, end - base);
        int li = base + lane; if (li >= end) li = end - 1;
        int sl = g_srcs[li];

#pragma unroll
        for (int c = 0; c < 8; c++) {
            int eslot = c * 4 + grp;
            int esrc = __shfl_sync(0xffffffffu, sl, eslot);
            if (eslot < cnt) {
                float a = g_asrc1[esrc * 8 + myh] + adst_l;
                a = a > 0.f ? a : 0.2f * a;
                float w = __expf(a);
                wsum += w;
                wsm[wid][eslot][myh] = w;
            }
        }
        __syncwarp();

#pragma unroll 8
        for (int d = 0; d < cnt; d++) {
            int src = __shfl_sync(0xffffffffu, sl, d);
            float w0 = wsm[wid][d][h0];
            float w1 = wsm[wid][d][h1f];
            const float* hp = &g_h1[(size_t)src * 64];
            acc0 = fmaf(w0, hp[lane],      acc0);
            acc1 = fmaf(w1, hp[32 + lane], acc1);
        }
        __syncwarp();
    }
    wsum += __shfl_xor_sync(0xffffffffu, wsum, 8);
    wsum += __shfl_xor_sync(0xffffffffu, wsum, 16);
    {
        float a = g_asrc1[node * 8 + myh] + adst_l;
        a = a > 0.f ? a : 0.2f * a;
        float wself = __expf(a);
        wsum += wself;
        float w0 = __shfl_sync(0xffffffffu, wself, h0);
        float w1 = __shfl_sync(0xffffffffu, wself, h1f);
        const float* hp = &g_h1[(size_t)node * 64];
        acc0 = fmaf(w0, hp[lane],      acc0);
        acc1 = fmaf(w1, hp[32 + lane], acc1);
    }
    float s0 = __shfl_sync(0xffffffffu, wsum, h0);
    float s1 = __shfl_sync(0xffffffffu, wsum, h1f);
    float t0 = acc0 / (s0 + 1e-16f) + b1[lane];
    float t1 = acc1 / (s1 + 1e-16f) + b1[32 + lane];
    t0 = t0 > 0.f ? t0 : expm1f(t0);
    t1 = t1 > 0.f ? t1 : expm1f(t1);
    g_hf1[(size_t)node * 64 + lane]      = t0;
    g_hf1[(size_t)node * 64 + 32 + lane] = t1;

    // layer-2 per-node logits (fused; v_s/v_d precomputed)
    float ps = t0 * g_vs2[lane] + t1 * g_vs2[32 + lane];
    float pd = t0 * g_vd2[lane] + t1 * g_vd2[32 + lane];
#pragma unroll
    for (int o = 16; o; o >>= 1) {
        ps += __shfl_xor_sync(0xffffffffu, ps, o);
        pd += __shfl_xor_sync(0xffffffffu, pd, o);
    }
    if (lane == 0) {
        g_asrc2[node] = ps;
        g_adst2[node] = pd;
    }
}

// ======  layer-2: aggregate hfeat, then W2 + b2 + log_softmax (fused)  ======
__global__ void agg2_kernel(const float* __restrict__ W2, const float* __restrict__ b2,
                            float* __restrict__ out, int n) {
    __shared__ float W2s[64 * 40];            // 10240 B
    __shared__ float hs[8][64];
    const int tid  = threadIdx.x;
    const int wid  = tid >> 5;
    const int lane = tid & 31;

    // cooperative W2 load (before any early exit!)
#pragma unroll
    for (int i = tid; i < 64 * 40; i += 256) W2s[i] = W2[i];
    __syncthreads();

    int node = (blockIdx.x * blockDim.x + tid) >> 5;
    if (node >= n) return;

    float adst = g_adst2[node];
    float acc0 = 0.f, acc1 = 0.f, ssum = 0.f;

    int beg = g_rowstart[node], end = g_rowstart[node + 1];
    for (int base = beg; base < end; base += 32) {
        int cnt = min(32, end - base);
        int sl = 0;
        float wl = 0.f;
        if (base + lane < end) {
            sl = g_srcs[base + lane];
            float a = g_asrc2[sl] + adst;
            a = a > 0.f ? a : 0.2f * a;
            wl = __expf(a);
            ssum += wl;
        }
#pragma unroll 8
        for (int d = 0; d < cnt; d++) {
            int src = __shfl_sync(0xffffffffu, sl, d);
            float w  = __shfl_sync(0xffffffffu, wl, d);
            const float* hp = &g_hf1[(size_t)src * 64];
            acc0 = fmaf(w, hp[lane],      acc0);
            acc1 = fmaf(w, hp[32 + lane], acc1);
        }
    }
#pragma unroll
    for (int o = 16; o; o >>= 1) ssum += __shfl_xor_sync(0xffffffffu, ssum, o);
    {   // self loop
        float a = g_asrc2[node] + adst;
        a = a > 0.f ? a : 0.2f * a;
        float w = __expf(a);
        ssum += w;
        const float* hp = &g_hf1[(size_t)node * 64];
        acc0 = fmaf(w, hp[lane],      acc0);
        acc1 = fmaf(w, hp[32 + lane], acc1);
    }
    float inv = 1.f / (ssum + 1e-16f);
    hs[wid][lane]      = acc0 * inv;
    hs[wid][32 + lane] = acc1 * inv;
    __syncwarp();

    // y = hs @ W2 + b2  (lane -> col lane; lane<8 also col 32+lane)
    float v0 = 0.f, v1 = 0.f;
    const float* hrow = hs[wid];
#pragma unroll
    for (int k = 0; k < 64; k++) {
        float hv = hrow[k];
        v0 = fmaf(hv, W2s[k * 40 + lane], v0);
        if (lane < 8) v1 = fmaf(hv, W2s[k * 40 + 32 + lane], v1);
    }
    v0 += __ldg(&b2[lane]);
    v1 = (lane < 8) ? v1 + __ldg(&b2[32 + lane]) : -3.4e38f;

    float m = fmaxf(v0, v1);
#pragma unroll
    for (int o = 16; o; o >>= 1) m = fmaxf(m, __shfl_xor_sync(0xffffffffu, m, o));
    float es = expf(v0 - m) + (lane < 8 ? expf(v1 - m) : 0.f);
#pragma unroll
    for (int o = 16; o; o >>= 1) es += __shfl_xor_sync(0xffffffffu, es, o);
    float lse = m + logf(es);

    float* dr = &out[(size_t)node * 40];
    dr[lane] = v0 - lse;
    if (lane < 8) dr[32 + lane] = v1 - lse;
}

// ---------------- launch -----------------------------------------------------
static inline int cdiv(int a, int b) { return (a + b - 1) / b; }

extern "C" void kernel_launch(void* const* d_in, const int* in_sizes, int n_in,
                              void* d_out, int out_size) {
    const float* x   = (const float*)d_in[0];
    const int*   ei  = (const int*)d_in[1];
    const float* W1  = (const float*)d_in[2];
    const float* as1 = (const float*)d_in[3];
    const float* ad1 = (const float*)d_in[4];
    const float* b1  = (const float*)d_in[5];
    const float* W2  = (const float*)d_in[6];
    const float* as2 = (const float*)d_in[7];
    const float* ad2 = (const float*)d_in[8];
    const float* b2  = (const float*)d_in[9];
    float*       out = (float*)d_out;

    const int n = in_sizes[0] / 512;      // 100000
    const int E = in_sizes[1] / 2;        // 1600000
    const int SMEM_G1 = 1024 + 2 * (2 * 10240 + 2 * 5120);   // 62464

    float *p_h1, *p_as1, *p_ad1;
    void* p_counts;
    cudaGetSymbolAddress((void**)&p_h1,  g_h1);
    cudaGetSymbolAddress((void**)&p_as1, g_asrc1);
    cudaGetSymbolAddress((void**)&p_ad1, g_adst1);
    cudaGetSymbolAddress(&p_counts, g_counts);

    static cudaStream_t s1 = nullptr, s2 = nullptr;
    static cudaEvent_t ev_fork = nullptr, ev_w = nullptr, ev_w2 = nullptr,
                       ev_g1 = nullptr, ev_csr = nullptr, ev_b = nullptr;
    if (s1 == nullptr) {
        cudaStreamCreateWithFlags(&s1, cudaStreamNonBlocking);
        cudaStreamCreateWithFlags(&s2, cudaStreamNonBlocking);
        cudaEventCreateWithFlags(&ev_fork, cudaEventDisableTiming);
        cudaEventCreateWithFlags(&ev_w,    cudaEventDisableTiming);
        cudaEventCreateWithFlags(&ev_w2,   cudaEventDisableTiming);
        cudaEventCreateWithFlags(&ev_g1,   cudaEventDisableTiming);
        cudaEventCreateWithFlags(&ev_csr,  cudaEventDisableTiming);
        cudaEventCreateWithFlags(&ev_b,    cudaEventDisableTiming);
        cudaFuncSetAttribute(gemm1_v2, cudaFuncAttributeMaxDynamicSharedMemorySize, SMEM_G1);
    }

    const int nb_scan = cdiv(n, 1024);
    const int nA = ((n / 2) + 255) & ~255;
    const int nB = n - nA;

    // ---- fork -------------------------------------------------------------
    cudaEventRecord(ev_fork, 0);
    cudaStreamWaitEvent(s1, ev_fork, 0);
    cudaStreamWaitEvent(s2, ev_fork, 0);

    cudaMemsetAsync(p_counts, 0, n * sizeof(int), s1);
    hist_kernel <<<cdiv(E, 256), 256, 0, s1>>>(ei, E);                 // (1)
    scan_part1  <<<nb_scan, 1024, 0, s1>>>(n);                         // (2)

    wprep_kernel<<<128, 256, 0, s2>>>(W1);                             // (3)
    cudaEventRecord(ev_w, s2);

    cudaStreamWaitEvent(0, ev_w, 0);
    gemm1_v2<<<cdiv(n, 128), 256, SMEM_G1>>>(x, n, p_h1,               // (4) profiled
                                             as1, ad1, p_as1, p_ad1);
    cudaEventRecord(ev_g1, 0);

    wprep2_kernel<<<1, 64, 0, s2>>>(W2, as2, ad2);                     // (5)
    cudaEventRecord(ev_w2, s2);

    scan_part23 <<<nb_scan, 1024, 0, s1>>>(nb_scan, n, E);             // (6)
    scatter_kernel<<<cdiv(E, 256), 256, 0, s1>>>(ei, E);               // (7)
    cudaEventRecord(ev_csr, s1);

    // ---- agg1 halves on two streams (both need gemm1 + CSR + wprep2) -------
    cudaStreamWaitEvent(s1, ev_g1, 0);
    cudaStreamWaitEvent(s1, ev_w2, 0);
    agg1_kernel<<<cdiv(nB * 32, 256), 256, 0, s1>>>(b1, nA, n);
    cudaEventRecord(ev_b, s1);

    cudaStreamWaitEvent(0, ev_csr, 0);
    cudaStreamWaitEvent(0, ev_w2, 0);
    agg1_kernel<<<cdiv(nA * 32, 256), 256>>>(b1, 0, nA);

    // ---- layer 2: single fused aggregate+W2+log_softmax --------------------
    cudaStreamWaitEvent(0, ev_b, 0);
    agg2_kernel<<<cdiv(n * 32, 256), 256>>>(W2, b2, out, n);
}

// round 14
// speedup vs baseline: 1.3779x; 1.3779x over previous
#include <cuda_runtime.h>
#include <cuda_bf16.h>
#include <math.h>
#include <stdint.h>

#define NMAX 100000
#define EMAX 1600000

// ---------------- scratch (static __device__, per harness rules) -------------
__device__ float g_h1[NMAX * 64];
__device__ float g_asrc1[NMAX * 8];
__device__ float g_adst1[NMAX * 8];
__device__ float g_hf1[NMAX * 64];
__device__ float g_h2[NMAX * 40];
__device__ float g_asrc2[NMAX];
__device__ float g_adst2[NMAX];

__device__ __nv_bfloat16 g_w1h[64 * 512];   // W1 transposed [n][k], bf16 hi
__device__ __nv_bfloat16 g_w1l[64 * 512];   // W1 transposed [n][k], bf16 lo

__device__ int g_counts[NMAX];
__device__ int g_cursor[NMAX];
__device__ int g_bsum[256];
__device__ int g_rowstart[NMAX + 1];
__device__ int g_srcs[EMAX];

// =======================  helpers  ==========================================

__device__ __forceinline__ uint32_t smem_u32(const void* p) {
    uint32_t a;
    asm("{ .reg .u64 t; cvta.to.shared.u64 t, %1; cvt.u32.u64 %0, t; }" : "=r"(a) : "l"(p));
    return a;
}

#define CP_ASYNC16(dst, src) \
    asm volatile("cp.async.cg.shared.global [%0], [%1], 16;" :: "r"(dst), "l"(src) : "memory")
#define CP_COMMIT() asm volatile("cp.async.commit_group;" ::: "memory")
#define CP_WAIT0()  asm volatile("cp.async.wait_group 0;" ::: "memory")

#define LDSM4(r, a) \
    asm volatile("ldmatrix.sync.aligned.m8n8.x4.shared.b16 {%0,%1,%2,%3}, [%4];" \
                 : "=r"((r)[0]), "=r"((r)[1]), "=r"((r)[2]), "=r"((r)[3]) : "r"(a))

__device__ __forceinline__ void mma_bf16(float& c0, float& c1, float& c2, float& c3,
                                         uint32_t a0, uint32_t a1, uint32_t a2, uint32_t a3,
                                         uint32_t b0, uint32_t b1) {
    asm volatile("mma.sync.aligned.m16n8k16.row.col.f32.bf16.bf16.f32 "
                 "{%0,%1,%2,%3}, {%4,%5,%6,%7}, {%8,%9}, {%0,%1,%2,%3};"
                 : "+f"(c0), "+f"(c1), "+f"(c2), "+f"(c3)
                 : "r"(a0), "r"(a1), "r"(a2), "r"(a3), "r"(b0), "r"(b1));
}

__device__ __forceinline__ void split_bf16(float v, __nv_bfloat16& hi, __nv_bfloat16& lo) {
    hi = __float2bfloat16(v);
    lo = __float2bfloat16(v - __bfloat162float(hi));
}
__device__ __forceinline__ uint32_t pack2(__nv_bfloat16 a, __nv_bfloat16 b) {
    return (uint32_t)__bfloat16_as_ushort(a) | ((uint32_t)__bfloat16_as_ushort(b) << 16);
}

// =======================  CSR build  ========================================

__global__ void hist_kernel(const int* __restrict__ ei, int E) {
    int e = blockIdx.x * blockDim.x + threadIdx.x;
    if (e >= E) return;
    atomicAdd(&g_counts[ei[E + e]], 1);
}

__global__ void scan_part1(int n) {
    __shared__ int sh[1024];
    int i = blockIdx.x * 1024 + threadIdx.x;
    sh[threadIdx.x] = (i < n) ? g_counts[i] : 0;
    __syncthreads();
#pragma unroll
    for (int off = 512; off; off >>= 1) {
        if (threadIdx.x < off) sh[threadIdx.x] += sh[threadIdx.x + off];
        __syncthreads();
    }
    if (threadIdx.x == 0) g_bsum[blockIdx.x] = sh[0];
}

__global__ void scan_part23(int nb, int n, int E) {
    __shared__ int sh[1024];
    __shared__ int soff;
    int t = threadIdx.x;
    int b = blockIdx.x;
    if (t < 32) {
        int acc = 0;
        for (int i = t; i < b; i += 32) acc += g_bsum[i];
#pragma unroll
        for (int o = 16; o; o >>= 1) acc += __shfl_xor_sync(0xffffffffu, acc, o);
        if (t == 0) soff = acc;
    }
    int i = b * 1024 + t;
    int v = (i < n) ? g_counts[i] : 0;
    sh[t] = v;
    __syncthreads();
#pragma unroll
    for (int off = 1; off < 1024; off <<= 1) {
        int add = (t >= off) ? sh[t - off] : 0;
        __syncthreads();
        sh[t] += add;
        __syncthreads();
    }
    if (i < n) {
        int ex = sh[t] - v + soff;
        g_rowstart[i] = ex;
        g_cursor[i]   = ex;
    }
    if (b == nb - 1 && t == 0) g_rowstart[n] = E;
}

__global__ void scatter_kernel(const int* __restrict__ ei, int E) {
    int e = blockIdx.x * blockDim.x + threadIdx.x;
    if (e >= E) return;
    int src = ei[e];
    int dst = ei[E + e];
    int pos = atomicAdd(&g_cursor[dst], 1);
    g_srcs[pos] = src;
}

// ===================  W1 prep: transpose + bf16 hi/lo split  =================
__global__ void wprep_kernel(const float* __restrict__ W1) {
    int i = blockIdx.x * 256 + threadIdx.x;   // 32768
    int n = i >> 9, k = i & 511;
    float v = W1[(size_t)k * 64 + n];
    __nv_bfloat16 h, l;
    split_bf16(v, h, l);
    g_w1h[i] = h;
    g_w1l[i] = l;
}

// ============  layer-1 GEMM: bf16 3-pass, double-buffered + ldmatrix  ========
__global__ __launch_bounds__(256, 3)
void gemm1_v2(const float* __restrict__ A, int M, float* __restrict__ C,
              const float* __restrict__ att_s, const float* __restrict__ att_d,
              float* __restrict__ asrc, float* __restrict__ adst) {
    extern __shared__ char dsm[];
    constexpr int STR  = 40;
    constexpr int SZ_A = 128 * STR * 2;       // 10240 B
    constexpr int SZ_B = 64 * STR * 2;        // 5120 B
    constexpr int STAGE = 2 * SZ_A + 2 * SZ_B;// 30720 B
    constexpr int OFF  = 1024;

    const int tid  = threadIdx.x;
    const int lane = tid & 31;
    const int warp = tid >> 5;
    const int wrow = warp >> 1;
    const int wcol = warp & 1;
    const int row0 = blockIdx.x * 128;
    const uint32_t smb = smem_u32(dsm);

    const int arow  = tid & 127;
    const int khalf = (tid >> 7) * 16;
    const int grow  = row0 + arow;
    const bool av   = (grow < M);
    const float* ap = A + (size_t)grow * 512 + khalf;

    float acc[2][4][4];
#pragma unroll
    for (int mt = 0; mt < 2; mt++)
#pragma unroll
        for (int nt = 0; nt < 4; nt++)
#pragma unroll
            for (int r = 0; r < 4; r++) acc[mt][nt][r] = 0.f;

    float rA[16];
    auto ldgA = [&](int kt) {
        if (av) {
#pragma unroll
            for (int q = 0; q < 4; q++)
                *reinterpret_cast<float4*>(&rA[q * 4]) =
                    *reinterpret_cast<const float4*>(ap + kt * 32 + q * 4);
        } else {
#pragma unroll
            for (int q = 0; q < 16; q++) rA[q] = 0.f;
        }
    };
    auto stsA = [&](int st) {
        uint32_t h[8], l[8];
#pragma unroll
        for (int p = 0; p < 8; p++) {
            __nv_bfloat16 h0, l0, h1, l1;
            split_bf16(rA[2 * p], h0, l0);
            split_bf16(rA[2 * p + 1], h1, l1);
            h[p] = pack2(h0, h1);
            l[p] = pack2(l0, l1);
        }
        char* base = dsm + OFF + st * STAGE;
        uint32_t off = (uint32_t)(arow * STR + khalf) * 2;
        *reinterpret_cast<uint4*>(base + off)             = make_uint4(h[0], h[1], h[2], h[3]);
        *reinterpret_cast<uint4*>(base + off + 16)        = make_uint4(h[4], h[5], h[6], h[7]);
        *reinterpret_cast<uint4*>(base + SZ_A + off)      = make_uint4(l[0], l[1], l[2], l[3]);
        *reinterpret_cast<uint4*>(base + SZ_A + off + 16) = make_uint4(l[4], l[5], l[6], l[7]);
    };
    auto cpB = [&](int kt, int st) {
        int nn = tid >> 2, kseg = tid & 3;
        uint32_t dst = smb + OFF + st * STAGE + 2 * SZ_A + (uint32_t)(nn * STR + kseg * 8) * 2;
        CP_ASYNC16(dst,        g_w1h + nn * 512 + kt * 32 + kseg * 8);
        CP_ASYNC16(dst + SZ_B, g_w1l + nn * 512 + kt * 32 + kseg * 8);
    };
    auto compute = [&](int st) {
        uint32_t sb = smb + OFF + st * STAGE;
#pragma unroll
        for (int ks = 0; ks < 2; ks++) {
            uint32_t a0addr = sb + (uint32_t)((wrow * 32 + (lane & 15)) * STR +
                                              (lane >> 4) * 8 + ks * 16) * 2;
            uint32_t ah[2][4], al[2][4];
#pragma unroll
            for (int mt = 0; mt < 2; mt++) {
                uint32_t ad = a0addr + mt * 16 * STR * 2;
                LDSM4(ah[mt], ad);
                LDSM4(al[mt], ad + SZ_A);
            }
#pragma unroll
            for (int np = 0; np < 2; np++) {
                uint32_t bd = sb + 2 * SZ_A +
                              (uint32_t)((wcol * 32 + np * 16 + ((lane >> 4) << 3) + (lane & 7)) * STR +
                                         ks * 16 + (((lane >> 3) & 1) << 3)) * 2;
                uint32_t bh4[4], bl4[4];
                LDSM4(bh4, bd);
                LDSM4(bl4, bd + SZ_B);
#pragma unroll
                for (int n2 = 0; n2 < 2; n2++) {
                    int nt = np * 2 + n2;
                    uint32_t b0h = bh4[n2 * 2], b1h = bh4[n2 * 2 + 1];
                    uint32_t b0l = bl4[n2 * 2], b1l = bl4[n2 * 2 + 1];
#pragma unroll
                    for (int mt = 0; mt < 2; mt++) {
                        float* c = acc[mt][nt];
                        mma_bf16(c[0], c[1], c[2], c[3],
                                 al[mt][0], al[mt][1], al[mt][2], al[mt][3], b0h, b1h);
                        mma_bf16(c[0], c[1], c[2], c[3],
                                 ah[mt][0], ah[mt][1], ah[mt][2], ah[mt][3], b0l, b1l);
                        mma_bf16(c[0], c[1], c[2], c[3],
                                 ah[mt][0], ah[mt][1], ah[mt][2], ah[mt][3], b0h, b1h);
                    }
                }
            }
        }
    };

    ldgA(0);
    cpB(0, 0);
    CP_COMMIT();
    stsA(0);
    CP_WAIT0();
    __syncthreads();

    for (int kt = 0; kt < 16; kt++) {
        int cur = kt & 1;
        if (kt < 15) {
            ldgA(kt + 1);
            cpB(kt + 1, cur ^ 1);
            CP_COMMIT();
        }
        compute(cur);
        if (kt < 15) {
            stsA(cur ^ 1);
            CP_WAIT0();
        }
        __syncthreads();
    }

    const int qt = lane & 3;
    const int rg = lane >> 2;
#pragma unroll
    for (int mt = 0; mt < 2; mt++)
#pragma unroll
        for (int nt = 0; nt < 4; nt++) {
            float* c = acc[mt][nt];
            int r0 = row0 + wrow * 32 + mt * 16 + rg;
            int r1 = r0 + 8;
            int col = wcol * 32 + nt * 8 + qt * 2;
            if (r0 < M)
                *reinterpret_cast<float2*>(&C[(size_t)r0 * 64 + col]) = make_float2(c[0], c[1]);
            if (r1 < M)
                *reinterpret_cast<float2*>(&C[(size_t)r1 * 64 + col]) = make_float2(c[2], c[3]);
            float s0 = __ldg(&att_s[col]), s1 = __ldg(&att_s[col + 1]);
            float d0 = __ldg(&att_d[col]), d1 = __ldg(&att_d[col + 1]);
            float as_a = c[0] * s0 + c[1] * s1;
            float ad_a = c[0] * d0 + c[1] * d1;
            float as_b = c[2] * s0 + c[3] * s1;
            float ad_b = c[2] * d0 + c[3] * d1;
            as_a += __shfl_xor_sync(0xffffffffu, as_a, 1);
            as_a += __shfl_xor_sync(0xffffffffu, as_a, 2);
            ad_a += __shfl_xor_sync(0xffffffffu, ad_a, 1);
            ad_a += __shfl_xor_sync(0xffffffffu, ad_a, 2);
            as_b += __shfl_xor_sync(0xffffffffu, as_b, 1);
            as_b += __shfl_xor_sync(0xffffffffu, as_b, 2);
            ad_b += __shfl_xor_sync(0xffffffffu, ad_b, 1);
            ad_b += __shfl_xor_sync(0xffffffffu, ad_b, 2);
            int head = wcol * 4 + nt;
            if (qt == 0) {
                if (r0 < M) { asrc[r0 * 8 + head] = as_a; adst[r0 * 8 + head] = ad_a; }
                if (r1 < M) { asrc[r1 * 8 + head] = as_b; adst[r1 * 8 + head] = ad_b; }
            }
        }
}

// =======================  layer-2 GEMM (SIMT, fused logits)  ================
template <int BCOLS, int TN, int KTILE>
__global__ void gemm2_kernel(const float* __restrict__ A, int M, int K,
                             const float* __restrict__ W, float* __restrict__ C,
                             const float* __restrict__ att_s, const float* __restrict__ att_d,
                             float* __restrict__ asrc, float* __restrict__ adst) {
    constexpr int BROWS = 256;
    constexpr int TM = 8;
    constexpr int TX = BCOLS / TN;
    constexpr int NT = TX * (BROWS / TM);
    constexpr int PAD = 4;

    __shared__ float xT[KTILE][BROWS + PAD];
    __shared__ float wS[KTILE][BCOLS];
    __shared__ float sAs[BCOLS], sAd[BCOLS];

    const int tid = threadIdx.x;
    const int tx = tid % TX;
    const int ty = tid / TX;
    const int row0 = blockIdx.x * BROWS;

    if (tid < BCOLS) { sAs[tid] = att_s[tid]; sAd[tid] = att_d[tid]; }

    float acc[TM][TN];
#pragma unroll
    for (int i = 0; i < TM; i++)
#pragma unroll
        for (int j = 0; j < TN; j++) acc[i][j] = 0.0f;

    for (int kt = 0; kt < K; kt += KTILE) {
        constexpr int KV = KTILE / 4;
        constexpr int XV = BROWS * KV;
#pragma unroll
        for (int v = tid; v < XV; v += NT) {
            int r  = v / KV;
            int kv = v % KV;
            int grow = row0 + r;
            float4 f = make_float4(0.f, 0.f, 0.f, 0.f);
            if (grow < M)
                f = *reinterpret_cast<const float4*>(&A[(size_t)grow * K + kt + kv * 4]);
            xT[kv * 4 + 0][r] = f.x;
            xT[kv * 4 + 1][r] = f.y;
            xT[kv * 4 + 2][r] = f.z;
            xT[kv * 4 + 3][r] = f.w;
        }
        constexpr int WV = KTILE * BCOLS / 4;
#pragma unroll
        for (int v = tid; v < WV; v += NT) {
            int k = v / (BCOLS / 4);
            int c = v % (BCOLS / 4);
            *reinterpret_cast<float4*>(&wS[k][c * 4]) =
                *reinterpret_cast<const float4*>(&W[(size_t)(kt + k) * BCOLS + c * 4]);
        }
        __syncthreads();

#pragma unroll
        for (int k = 0; k < KTILE; k++) {
            float a[TM];
            *reinterpret_cast<float4*>(&a[0]) = *reinterpret_cast<float4*>(&xT[k][ty * TM]);
            *reinterpret_cast<float4*>(&a[4]) = *reinterpret_cast<float4*>(&xT[k][ty * TM + 4]);
            float b[TN];
#pragma unroll
            for (int j = 0; j < TN; j++) b[j] = wS[k][tx * TN + j];
#pragma unroll
            for (int i = 0; i < TM; i++)
#pragma unroll
                for (int j = 0; j < TN; j++) acc[i][j] = fmaf(a[i], b[j], acc[i][j]);
        }
        __syncthreads();
    }

#pragma unroll
    for (int i = 0; i < TM; i++) {
        int grow = row0 + ty * TM + i;
        if (grow < M) {
#pragma unroll
            for (int j = 0; j < TN; j++) C[(size_t)grow * BCOLS + tx * TN + j] = acc[i][j];
        }
        float as = 0.f, ad = 0.f;
#pragma unroll
        for (int j = 0; j < TN; j++) {
            as = fmaf(acc[i][j], sAs[tx * TN + j], as);
            ad = fmaf(acc[i][j], sAd[tx * TN + j], ad);
        }
#pragma unroll
        for (int off = 4; off; off >>= 1) {
            as += __shfl_xor_sync(0xffffffffu, as, off);
            ad += __shfl_xor_sync(0xffffffffu, ad, off);
        }
        if (tx == 0 && grow < M) { asrc[grow] = as; adst[grow] = ad; }
    }
}

// ========  layer-1 aggregation: 8 lanes per node (lane sub = head sub)  ======
// Lane (node, sub) accumulates features [8*sub .. 8*sub+7] (= head sub) and
// its own weight sum. No shfl/smem in the loop; 4 independent nodes per warp.
__global__ void agg1_kernel(const float* __restrict__ b1, int node0, int node1) {
    int gt = blockIdx.x * blockDim.x + threadIdx.x;
    int node = node0 + (gt >> 3);
    int sub  = gt & 7;
    if (node >= node1) return;

    float adst = __ldg(&g_adst1[node * 8 + sub]);
    float4 aA = make_float4(0.f, 0.f, 0.f, 0.f);
    float4 aB = make_float4(0.f, 0.f, 0.f, 0.f);
    float wsum = 0.f;

    int beg = g_rowstart[node], end = g_rowstart[node + 1];
#pragma unroll 4
    for (int i = beg; i < end; i++) {
        int src = __ldg(&g_srcs[i]);
        float a = __ldg(&g_asrc1[src * 8 + sub]) + adst;
        a = a > 0.f ? a : 0.2f * a;
        float w = __expf(a);
        wsum += w;
        const float4* hp = reinterpret_cast<const float4*>(&g_h1[(size_t)src * 64 + sub * 8]);
        float4 h0 = __ldg(hp);
        float4 h1v = __ldg(hp + 1);
        aA.x = fmaf(w, h0.x, aA.x);  aA.y = fmaf(w, h0.y, aA.y);
        aA.z = fmaf(w, h0.z, aA.z);  aA.w = fmaf(w, h0.w, aA.w);
        aB.x = fmaf(w, h1v.x, aB.x); aB.y = fmaf(w, h1v.y, aB.y);
        aB.z = fmaf(w, h1v.z, aB.z); aB.w = fmaf(w, h1v.w, aB.w);
    }
    // self loop
    {
        float a = __ldg(&g_asrc1[node * 8 + sub]) + adst;
        a = a > 0.f ? a : 0.2f * a;
        float w = __expf(a);
        wsum += w;
        const float4* hp = reinterpret_cast<const float4*>(&g_h1[(size_t)node * 64 + sub * 8]);
        float4 h0 = __ldg(hp);
        float4 h1v = __ldg(hp + 1);
        aA.x = fmaf(w, h0.x, aA.x);  aA.y = fmaf(w, h0.y, aA.y);
        aA.z = fmaf(w, h0.z, aA.z);  aA.w = fmaf(w, h0.w, aA.w);
        aB.x = fmaf(w, h1v.x, aB.x); aB.y = fmaf(w, h1v.y, aB.y);
        aB.z = fmaf(w, h1v.z, aB.z); aB.w = fmaf(w, h1v.w, aB.w);
    }
    float inv = 1.f / (wsum + 1e-16f);
    const float4* bp = reinterpret_cast<const float4*>(&b1[sub * 8]);
    float4 b0 = __ldg(bp);
    float4 b1v = __ldg(bp + 1);
    float4 o0, o1;
    o0.x = aA.x * inv + b0.x;  o0.y = aA.y * inv + b0.y;
    o0.z = aA.z * inv + b0.z;  o0.w = aA.w * inv + b0.w;
    o1.x = aB.x * inv + b1v.x; o1.y = aB.y * inv + b1v.y;
    o1.z = aB.z * inv + b1v.z; o1.w = aB.w * inv + b1v.w;
    o0.x = o0.x > 0.f ? o0.x : expm1f(o0.x);
    o0.y = o0.y > 0.f ? o0.y : expm1f(o0.y);
    o0.z = o0.z > 0.f ? o0.z : expm1f(o0.z);
    o0.w = o0.w > 0.f ? o0.w : expm1f(o0.w);
    o1.x = o1.x > 0.f ? o1.x : expm1f(o1.x);
    o1.y = o1.y > 0.f ? o1.y : expm1f(o1.y);
    o1.z = o1.z > 0.f ? o1.z : expm1f(o1.z);
    o1.w = o1.w > 0.f ? o1.w : expm1f(o1.w);
    float4* op = reinterpret_cast<float4*>(&g_hf1[(size_t)node * 64 + sub * 8]);
    op[0] = o0;
    op[1] = o1;
}

// ======  layer-2 aggregation: 8 lanes per node + fused log_softmax  =========
// Lane sub owns features [4*sub..4*sub+3] and feature 32+sub (5 values).
__global__ void agg2_kernel(const float* __restrict__ b2, float* __restrict__ out, int n) {
    int gt = blockIdx.x * blockDim.x + threadIdx.x;
    int node = gt >> 3;
    int sub  = gt & 7;
    if (node >= n) return;

    float adst = __ldg(&g_adst2[node]);
    float4 a4 = make_float4(0.f, 0.f, 0.f, 0.f);
    float a1 = 0.f, wsum = 0.f;

    int beg = g_rowstart[node], end = g_rowstart[node + 1];
#pragma unroll 4
    for (int i = beg; i < end; i++) {
        int src = __ldg(&g_srcs[i]);
        float a = __ldg(&g_asrc2[src]) + adst;
        a = a > 0.f ? a : 0.2f * a;
        float w = __expf(a);
        wsum += w;
        const float* hp = &g_h2[(size_t)src * 40];
        float4 h4 = __ldg(reinterpret_cast<const float4*>(hp + sub * 4));
        float h1v = __ldg(hp + 32 + sub);
        a4.x = fmaf(w, h4.x, a4.x); a4.y = fmaf(w, h4.y, a4.y);
        a4.z = fmaf(w, h4.z, a4.z); a4.w = fmaf(w, h4.w, a4.w);
        a1 = fmaf(w, h1v, a1);
    }
    // self loop
    {
        float a = __ldg(&g_asrc2[node]) + adst;
        a = a > 0.f ? a : 0.2f * a;
        float w = __expf(a);
        wsum += w;
        const float* hp = &g_h2[(size_t)node * 40];
        float4 h4 = __ldg(reinterpret_cast<const float4*>(hp + sub * 4));
        float h1v = __ldg(hp + 32 + sub);
        a4.x = fmaf(w, h4.x, a4.x); a4.y = fmaf(w, h4.y, a4.y);
        a4.z = fmaf(w, h4.z, a4.z); a4.w = fmaf(w, h4.w, a4.w);
        a1 = fmaf(w, h1v, a1);
    }
    float inv = 1.f / (wsum + 1e-16f);
    float v[5];
    v[0] = a4.x * inv + __ldg(&b2[sub * 4 + 0]);
    v[1] = a4.y * inv + __ldg(&b2[sub * 4 + 1]);
    v[2] = a4.z * inv + __ldg(&b2[sub * 4 + 2]);
    v[3] = a4.w * inv + __ldg(&b2[sub * 4 + 3]);
    v[4] = a1   * inv + __ldg(&b2[32 + sub]);

    float m = v[0];
#pragma unroll
    for (int j = 1; j < 5; j++) m = fmaxf(m, v[j]);
#pragma unroll
    for (int o = 4; o; o >>= 1) m = fmaxf(m, __shfl_xor_sync(0xffffffffu, m, o));
    float es = 0.f;
#pragma unroll
    for (int j = 0; j < 5; j++) es += expf(v[j] - m);
#pragma unroll
    for (int o = 4; o; o >>= 1) es += __shfl_xor_sync(0xffffffffu, es, o);
    float lse = m + logf(es);

    float* dr = &out[(size_t)node * 40];
    *reinterpret_cast<float4*>(dr + sub * 4) =
        make_float4(v[0] - lse, v[1] - lse, v[2] - lse, v[3] - lse);
    dr[32 + sub] = v[4] - lse;
}

// ---------------- launch -----------------------------------------------------
static inline int cdiv(int a, int b) { return (a + b - 1) / b; }

extern "C" void kernel_launch(void* const* d_in, const int* in_sizes, int n_in,
                              void* d_out, int out_size) {
    const float* x   = (const float*)d_in[0];
    const int*   ei  = (const int*)d_in[1];
    const float* W1  = (const float*)d_in[2];
    const float* as1 = (const float*)d_in[3];
    const float* ad1 = (const float*)d_in[4];
    const float* b1  = (const float*)d_in[5];
    const float* W2  = (const float*)d_in[6];
    const float* as2 = (const float*)d_in[7];
    const float* ad2 = (const float*)d_in[8];
    const float* b2  = (const float*)d_in[9];
    float*       out = (float*)d_out;

    const int n = in_sizes[0] / 512;      // 100000
    const int E = in_sizes[1] / 2;        // 1600000
    const int SMEM_G1 = 1024 + 2 * (2 * 10240 + 2 * 5120);   // 62464

    float *p_h1, *p_hf1, *p_h2, *p_as1, *p_ad1, *p_as2, *p_ad2;
    void* p_counts;
    cudaGetSymbolAddress((void**)&p_h1,  g_h1);
    cudaGetSymbolAddress((void**)&p_hf1, g_hf1);
    cudaGetSymbolAddress((void**)&p_h2,  g_h2);
    cudaGetSymbolAddress((void**)&p_as1, g_asrc1);
    cudaGetSymbolAddress((void**)&p_ad1, g_adst1);
    cudaGetSymbolAddress((void**)&p_as2, g_asrc2);
    cudaGetSymbolAddress((void**)&p_ad2, g_adst2);
    cudaGetSymbolAddress(&p_counts, g_counts);

    static cudaStream_t s1 = nullptr, s2 = nullptr;
    static cudaEvent_t ev_fork = nullptr, ev_w = nullptr, ev_g1 = nullptr,
                       ev_csr = nullptr, ev_b = nullptr;
    if (s1 == nullptr) {
        cudaStreamCreateWithFlags(&s1, cudaStreamNonBlocking);
        cudaStreamCreateWithFlags(&s2, cudaStreamNonBlocking);
        cudaEventCreateWithFlags(&ev_fork, cudaEventDisableTiming);
        cudaEventCreateWithFlags(&ev_w,    cudaEventDisableTiming);
        cudaEventCreateWithFlags(&ev_g1,   cudaEventDisableTiming);
        cudaEventCreateWithFlags(&ev_csr,  cudaEventDisableTiming);
        cudaEventCreateWithFlags(&ev_b,    cudaEventDisableTiming);
        cudaFuncSetAttribute(gemm1_v2, cudaFuncAttributeMaxDynamicSharedMemorySize, SMEM_G1);
    }

    const int nb_scan = cdiv(n, 1024);
    const int nA = ((n / 2) + 255) & ~255;
    const int nB = n - nA;

    // ---- fork -------------------------------------------------------------
    cudaEventRecord(ev_fork, 0);
    cudaStreamWaitEvent(s1, ev_fork, 0);
    cudaStreamWaitEvent(s2, ev_fork, 0);

    cudaMemsetAsync(p_counts, 0, n * sizeof(int), s1);                 // (1)
    hist_kernel <<<cdiv(E, 256), 256, 0, s1>>>(ei, E);                 // (2)
    scan_part1  <<<nb_scan, 1024, 0, s1>>>(n);                         // (3)

    wprep_kernel<<<128, 256, 0, s2>>>(W1);                             // (4)
    cudaEventRecord(ev_w, s2);

    cudaStreamWaitEvent(0, ev_w, 0);
    gemm1_v2<<<cdiv(n, 128), 256, SMEM_G1>>>(x, n, p_h1,               // (5) profiled
                                             as1, ad1, p_as1, p_ad1);
    cudaEventRecord(ev_g1, 0);

    scan_part23 <<<nb_scan, 1024, 0, s1>>>(nb_scan, n, E);             // (6)
    scatter_kernel<<<cdiv(E, 256), 256, 0, s1>>>(ei, E);               // (7)
    cudaEventRecord(ev_csr, s1);

    // ---- B half on s1 overlapping A half on main ---------------------------
    cudaStreamWaitEvent(s1, ev_g1, 0);
    agg1_kernel<<<cdiv(nB * 8, 256), 256, 0, s1>>>(b1, nA, n);
    gemm2_kernel<40, 5, 32><<<cdiv(nB, 256), 256, 0, s1>>>(
        p_hf1 + (size_t)nA * 64, nB, 64, W2, p_h2 + (size_t)nA * 40,
        as2, ad2, p_as2 + nA, p_ad2 + nA);
    cudaEventRecord(ev_b, s1);

    cudaStreamWaitEvent(0, ev_csr, 0);
    agg1_kernel<<<cdiv(nA * 8, 256), 256>>>(b1, 0, nA);
    gemm2_kernel<40, 5, 32><<<cdiv(nA, 256), 256>>>(
        p_hf1, nA, 64, W2, p_h2, as2, ad2, p_as2, p_ad2);

    cudaStreamWaitEvent(0, ev_b, 0);
    agg2_kernel<<<cdiv(n * 8, 256), 256>>>(b2, out, n);
}